// round 1
// baseline (speedup 1.0000x reference)
#include <cuda_runtime.h>
#include <cstdint>

// Problem constants (fixed per reference)
#define Bn 8
#define Hn 1080
#define Wn 1920
constexpr int HW  = Hn * Wn;        // 2,073,600
constexpr int BHW = Bn * HW;        // 16,588,800

// Scratch: interleaved accumulator {sum(-fx*w), sum(-fy*w), sum(w), pad}
__device__ float4        g_acc[BHW];     // ~265 MB (bss, module-load allocated)
__device__ unsigned char g_mask[BHW];    // count>0 flag

// ---------------------------------------------------------------------------
// Vector reduction: one 16B no-return atomic add instead of 3 scalar atomics.
// ---------------------------------------------------------------------------
__device__ __forceinline__ void red_add_v4(float4* p, float vx, float vy, float w) {
    asm volatile("red.global.add.v4.f32 [%0], {%1, %2, %3, %4};"
                 :: "l"(p), "f"(vx), "f"(vy), "f"(w), "f"(0.0f)
                 : "memory");
}

// ---------------------------------------------------------------------------
// 1) Zero the accumulator (must happen each graph replay)
// ---------------------------------------------------------------------------
__global__ void zero_kernel() {
    int i = blockIdx.x * blockDim.x + threadIdx.x;
    if (i < BHW) g_acc[i] = make_float4(0.f, 0.f, 0.f, 0.f);
}

// ---------------------------------------------------------------------------
// 2) Forward splat: each source pixel deposits (-fx*w, -fy*w, w) to the 4
//    integer corners around (x+fx, y+fy). Invalid targets deposit exactly 0
//    in the reference, so they are skipped.
// ---------------------------------------------------------------------------
__global__ void splat_kernel(const float* __restrict__ flow,
                             const float* __restrict__ depth) {
    int i = blockIdx.x * blockDim.x + threadIdx.x;
    if (i >= BHW) return;

    int b = i / HW;
    int p = i - b * HW;
    int y = p / Wn;
    int x = p - y * Wn;

    const float fx = flow[(size_t)b * 2 * HW + p];
    const float fy = flow[(size_t)b * 2 * HW + HW + p];

    float x2 = (float)x + fx;
    float y2 = (float)y + fy;

    // valid = in [0, W-1] x [0, H-1]; matches reference float32 comparisons
    if (!(x2 >= 0.0f && x2 <= (float)(Wn - 1) &&
          y2 >= 0.0f && y2 <= (float)(Hn - 1)))
        return;

    const float w  = depth[i];
    const float vx = -fx * w;
    const float vy = -fy * w;

    // floor == trunc for non-negative values (guaranteed by validity check)
    int ixL = (int)x2;
    int iyT = (int)y2;
    int ixR = min(ixL + 1, Wn - 1);
    int iyB = min(iyT + 1, Hn - 1);

    float4* base = g_acc + (size_t)b * HW;
    // 4 corners, unconditional (duplicate corners must deposit twice, as in ref)
    red_add_v4(base + iyT * Wn + ixL, vx, vy, w);
    red_add_v4(base + iyT * Wn + ixR, vx, vy, w);
    red_add_v4(base + iyB * Wn + ixL, vx, vy, w);
    red_add_v4(base + iyB * Wn + ixR, vx, vy, w);
}

// ---------------------------------------------------------------------------
// 3) Normalize: out = acc / max(count, "1 if zero"); record fill mask.
// ---------------------------------------------------------------------------
__global__ void normalize_kernel(float* __restrict__ out) {
    int i = blockIdx.x * blockDim.x + threadIdx.x;
    if (i >= BHW) return;

    float4 a   = g_acc[i];
    float  cnt = a.z;
    float  inv = 1.0f / (cnt > 0.0f ? cnt : 1.0f);

    int b = i / HW;
    int p = i - b * HW;

    out[(size_t)b * 2 * HW + p]      = a.x * inv;
    out[(size_t)b * 2 * HW + HW + p] = a.y * inv;
    g_mask[i] = (cnt > 0.0f) ? 1 : 0;
}

// ---------------------------------------------------------------------------
// 4) Hole fill: ~2% of pixels are holes (Poisson(4) coverage). For each hole,
//    walk the 4 axis directions to the nearest filled pixel (expected 1-2
//    steps) and average their out values. Writes only holes, reads only
//    filled pixels -> in-place on d_out is race-free.
// ---------------------------------------------------------------------------
__global__ void fill_kernel(float* __restrict__ out) {
    int i = blockIdx.x * blockDim.x + threadIdx.x;
    if (i >= BHW) return;
    if (g_mask[i]) return;   // filled pixel: already final

    int b = i / HW;
    int p = i - b * HW;
    int y = p / Wn;
    int x = p - y * Wn;

    const unsigned char* m  = g_mask + (size_t)b * HW;
    float*               o0 = out + (size_t)b * 2 * HW;
    float*               o1 = o0 + HW;

    float sx = 0.f, sy = 0.f;
    int   s  = 0;

    // left
    for (int xx = x - 1; xx >= 0; --xx) {
        int q = y * Wn + xx;
        if (m[q]) { sx += o0[q]; sy += o1[q]; s++; break; }
    }
    // right
    for (int xx = x + 1; xx < Wn; ++xx) {
        int q = y * Wn + xx;
        if (m[q]) { sx += o0[q]; sy += o1[q]; s++; break; }
    }
    // up
    for (int yy = y - 1; yy >= 0; --yy) {
        int q = yy * Wn + x;
        if (m[q]) { sx += o0[q]; sy += o1[q]; s++; break; }
    }
    // down
    for (int yy = y + 1; yy < Hn; ++yy) {
        int q = yy * Wn + x;
        if (m[q]) { sx += o0[q]; sy += o1[q]; s++; break; }
    }

    if (s > 0) {
        float inv = 1.0f / (float)s;
        o0[y * Wn + x] = sx * inv;
        o1[y * Wn + x] = sy * inv;
    }
    // s == 0: keep out (== 0 at holes, since count==0 implies acc.xy==0)
}

// ---------------------------------------------------------------------------
// Launch
// ---------------------------------------------------------------------------
extern "C" void kernel_launch(void* const* d_in, const int* in_sizes, int n_in,
                              void* d_out, int out_size) {
    const float* flow  = (const float*)d_in[0];   // (B, 2, H, W) fp32
    const float* depth = (const float*)d_in[1];   // (B, 1, H, W) fp32
    float*       out   = (float*)d_out;           // (B, 2, H, W) fp32

    const int threads = 256;
    const int blocks  = (BHW + threads - 1) / threads;

    zero_kernel<<<blocks, threads>>>();
    splat_kernel<<<blocks, threads>>>(flow, depth);
    normalize_kernel<<<blocks, threads>>>(out);
    fill_kernel<<<blocks, threads>>>(out);
}